// round 10
// baseline (speedup 1.0000x reference)
#include <cuda_runtime.h>
#include <cuda_fp16.h>
#include <math.h>

#define NNODES 50000
#define NADJ   6
#define NEDGE  800000
#define NH     256
#define LN_EPS 1e-5f

#define SCAN_B 1024
#define BLK_PER_ADJ ((NNODES + SCAN_B - 1) / SCAN_B)   // 49

// ---------------- device scratch (no allocations allowed) ----------------
static __device__ __align__(16) __half g_state0[(size_t)NNODES * NH];
static __device__ __align__(16) __half g_state1[(size_t)NNODES * NH];
static __device__ __align__(16) __half g_state2[(size_t)NNODES * NH];
static __device__ int   g_cnt[NADJ * NNODES];
static __device__ int   g_rowptr[NADJ * (NNODES + 1)];
static __device__ int   g_cur[NADJ * NNODES];
static __device__ int   g_blksum[NADJ * BLK_PER_ADJ];
static __device__ __align__(16) int2 g_edge[(size_t)NADJ * NEDGE];  // {col, val bits}
static __device__ int   g_adj_idx[6];   // [seq0,seq1,seq2,res0,res1,res2]
static __device__ int   g_used[NADJ];

// ---------------- idx decode: int32 vs int64 autodetect -------------------
__global__ void decode_idx_kernel(const int* __restrict__ seq_raw,
                                  const int* __restrict__ res_raw) {
    if (threadIdx.x != 0 || blockIdx.x != 0) return;
    long long a[6];
    int b[6];
    bool v64 = true, v32 = true;
    const long long* s64 = (const long long*)seq_raw;
    const long long* r64 = (const long long*)res_raw;
#pragma unroll
    for (int i = 0; i < 3; i++) {
        long long t = s64[i]; a[i] = t;     if (t < 0 || t >= NADJ) v64 = false;
        long long u = r64[i]; a[3 + i] = u; if (u < 0 || u >= NADJ) v64 = false;
        int p = seq_raw[i]; b[i] = p;       if (p < 0 || p >= NADJ) v32 = false;
        int q = res_raw[i]; b[3 + i] = q;   if (q < 0 || q >= NADJ) v32 = false;
    }
    (void)v32;
#pragma unroll
    for (int i = 0; i < NADJ; i++) g_used[i] = 0;
#pragma unroll
    for (int i = 0; i < 6; i++) {
        int v = v64 ? (int)a[i] : b[i];
        g_adj_idx[i] = v;
        g_used[v] = 1;
    }
}

// ---------------- CSR build --------------------------------------------
__global__ void zero_cnt_kernel() {
    int i = blockIdx.x * blockDim.x + threadIdx.x;
    if (i < NADJ * NNODES) g_cnt[i] = 0;
}

__global__ void hist_kernel(const int* __restrict__ rows) {
    int i = blockIdx.x * blockDim.x + threadIdx.x;
    if (i >= NADJ * NEDGE) return;
    int adj = i / NEDGE;
    if (!g_used[adj]) return;
    int r = rows[i];
    atomicAdd(&g_cnt[adj * NNODES + r], 1);
}

__global__ __launch_bounds__(SCAN_B) void scanA_kernel() {
    __shared__ int s[SCAN_B];
    int bx = blockIdx.x;
    int adj = bx / BLK_PER_ADJ;
    int blk = bx % BLK_PER_ADJ;
    int t = threadIdx.x;
    int i = blk * SCAN_B + t;
    int v = (i < NNODES) ? g_cnt[adj * NNODES + i] : 0;
    s[t] = v;
    __syncthreads();
#pragma unroll
    for (int off = 1; off < SCAN_B; off <<= 1) {
        int u = (t >= off) ? s[t - off] : 0;
        __syncthreads();
        s[t] += u;
        __syncthreads();
    }
    if (i < NNODES) g_cnt[adj * NNODES + i] = s[t] - v;
    if (t == SCAN_B - 1) g_blksum[adj * BLK_PER_ADJ + blk] = s[t];
}

__global__ __launch_bounds__(512) void scanB_kernel() {
    __shared__ int sb[NADJ * BLK_PER_ADJ];
    int t = threadIdx.x;
    for (int i = t; i < NADJ * BLK_PER_ADJ; i += blockDim.x) sb[i] = g_blksum[i];
    __syncthreads();
    if (t < NADJ) {
        int run = 0;
        for (int k = 0; k < BLK_PER_ADJ; k++) {
            int v = sb[t * BLK_PER_ADJ + k];
            sb[t * BLK_PER_ADJ + k] = run;
            run += v;
        }
        g_rowptr[t * (NNODES + 1) + NNODES] = run;
    }
    __syncthreads();
    for (int i = t; i < NADJ * BLK_PER_ADJ; i += blockDim.x) g_blksum[i] = sb[i];
}

__global__ __launch_bounds__(SCAN_B) void scanC_kernel() {
    int bx = blockIdx.x;
    int adj = bx / BLK_PER_ADJ;
    int blk = bx % BLK_PER_ADJ;
    int t = threadIdx.x;
    int i = blk * SCAN_B + t;
    if (i >= NNODES) return;
    int val = g_cnt[adj * NNODES + i] + g_blksum[adj * BLK_PER_ADJ + blk];
    g_rowptr[adj * (NNODES + 1) + i] = val;
    g_cur[adj * NNODES + i] = val;
}

__global__ void scatter_kernel(const int* __restrict__ rows,
                               const int* __restrict__ cols,
                               const float* __restrict__ vals) {
    int i = blockIdx.x * blockDim.x + threadIdx.x;
    if (i >= NADJ * NEDGE) return;
    int adj = i / NEDGE;
    if (!g_used[adj]) return;
    int r = rows[i];
    int pos = atomicAdd(&g_cur[adj * NNODES + r], 1);
    g_edge[(size_t)adj * NEDGE + pos] = make_int2(cols[i], __float_as_int(vals[i]));
}

// ---------------- TF32 split tensor-core GEMM, fp16 output ----------------
#define GBM 128
#define GBN 128
#define GBK 16
#define SPAD 20

__device__ __forceinline__ float f2tf32(float x) {
    float r;
    asm("cvt.rna.tf32.f32 %0, %1;" : "=f"(r) : "f"(x));
    return r;
}

__device__ __forceinline__ void mma_tf32(float* d, const float* a, float b0, float b1) {
    asm volatile(
        "mma.sync.aligned.m16n8k8.row.col.f32.tf32.tf32.f32 "
        "{%0,%1,%2,%3}, {%4,%5,%6,%7}, {%8,%9}, {%0,%1,%2,%3};"
        : "+f"(d[0]), "+f"(d[1]), "+f"(d[2]), "+f"(d[3])
        : "r"(__float_as_uint(a[0])), "r"(__float_as_uint(a[1])),
          "r"(__float_as_uint(a[2])), "r"(__float_as_uint(a[3])),
          "r"(__float_as_uint(b0)), "r"(__float_as_uint(b1)));
}

__global__ __launch_bounds__(256) void gemm_tf32_kernel(
    const float* __restrict__ A, const float* __restrict__ W,
    const float* __restrict__ bias, __half* __restrict__ C) {
    __shared__ float As_hi[GBM][SPAD];
    __shared__ float As_lo[GBM][SPAD];
    __shared__ float Bs_hi[GBN][SPAD];
    __shared__ float Bs_lo[GBN][SPAD];

    int t = threadIdx.x;
    int m0 = blockIdx.x * GBM;
    int n0 = blockIdx.y * GBN;
    int ws = t >> 5, lane = t & 31;
    int wm = ws & 3, wn = ws >> 2;
    int g = lane >> 2, t4 = lane & 3;

    float acc[2][8][4];
#pragma unroll
    for (int i = 0; i < 2; i++)
#pragma unroll
        for (int j = 0; j < 8; j++)
#pragma unroll
            for (int q = 0; q < 4; q++) acc[i][j][q] = 0.f;

    for (int k0 = 0; k0 < NH; k0 += GBK) {
#pragma unroll
        for (int L = 0; L < 2; L++) {
            int f = t + L * 256;
            int m = f >> 2, c4 = f & 3;
            int gm = m0 + m;
            float4 v = make_float4(0.f, 0.f, 0.f, 0.f);
            if (gm < NNODES)
                v = *(const float4*)(A + (size_t)gm * NH + k0 + c4 * 4);
            float4 h, l;
            h.x = f2tf32(v.x); l.x = f2tf32(v.x - h.x);
            h.y = f2tf32(v.y); l.y = f2tf32(v.y - h.y);
            h.z = f2tf32(v.z); l.z = f2tf32(v.z - h.z);
            h.w = f2tf32(v.w); l.w = f2tf32(v.w - h.w);
            *(float4*)&As_hi[m][c4 * 4] = h;
            *(float4*)&As_lo[m][c4 * 4] = l;
        }
#pragma unroll
        for (int L = 0; L < 2; L++) {
            int f = t + L * 256;
            int n = f >> 2, c4 = f & 3;
            float4 v = *(const float4*)(W + (size_t)(n0 + n) * NH + k0 + c4 * 4);
            float4 h, l;
            h.x = f2tf32(v.x); l.x = f2tf32(v.x - h.x);
            h.y = f2tf32(v.y); l.y = f2tf32(v.y - h.y);
            h.z = f2tf32(v.z); l.z = f2tf32(v.z - h.z);
            h.w = f2tf32(v.w); l.w = f2tf32(v.w - h.w);
            *(float4*)&Bs_hi[n][c4 * 4] = h;
            *(float4*)&Bs_lo[n][c4 * 4] = l;
        }
        __syncthreads();

#pragma unroll
        for (int k8 = 0; k8 < GBK / 8; k8++) {
            int kb = k8 * 8;
            float ah[2][4], al[2][4];
#pragma unroll
            for (int i = 0; i < 2; i++) {
                int mr = wm * 32 + i * 16;
                ah[i][0] = As_hi[mr + g][kb + t4];
                ah[i][1] = As_hi[mr + g + 8][kb + t4];
                ah[i][2] = As_hi[mr + g][kb + t4 + 4];
                ah[i][3] = As_hi[mr + g + 8][kb + t4 + 4];
                al[i][0] = As_lo[mr + g][kb + t4];
                al[i][1] = As_lo[mr + g + 8][kb + t4];
                al[i][2] = As_lo[mr + g][kb + t4 + 4];
                al[i][3] = As_lo[mr + g + 8][kb + t4 + 4];
            }
#pragma unroll
            for (int j = 0; j < 8; j++) {
                int nb = wn * 64 + j * 8;
                float b0h = Bs_hi[nb + g][kb + t4];
                float b1h = Bs_hi[nb + g][kb + t4 + 4];
                float b0l = Bs_lo[nb + g][kb + t4];
                float b1l = Bs_lo[nb + g][kb + t4 + 4];
#pragma unroll
                for (int i = 0; i < 2; i++) {
                    mma_tf32(acc[i][j], ah[i], b0h, b1h);
                    mma_tf32(acc[i][j], ah[i], b0l, b1l);
                    mma_tf32(acc[i][j], al[i], b0h, b1h);
                }
            }
        }
        __syncthreads();
    }

    // epilogue: + bias, convert to fp16, store half2
#pragma unroll
    for (int j = 0; j < 8; j++) {
        int c = n0 + wn * 64 + j * 8 + 2 * t4;
        float bx = __ldg(bias + c);
        float by = __ldg(bias + c + 1);
#pragma unroll
        for (int i = 0; i < 2; i++) {
            int r0 = m0 + wm * 32 + i * 16 + g;
            if (r0 < NNODES) {
                *(half2*)(C + (size_t)r0 * NH + c) =
                    __floats2half2_rn(acc[i][j][0] + bx, acc[i][j][1] + by);
            }
            int r1 = r0 + 8;
            if (r1 < NNODES) {
                *(half2*)(C + (size_t)r1 * NH + c) =
                    __floats2half2_rn(acc[i][j][2] + bx, acc[i][j][3] + by);
            }
        }
    }
}

// ---------------- CSR SpMM: warp-per-row, fp16 gather, fp32 accum ---------
// Each lane owns 8 consecutive cols (lane*8 .. lane*8+7) = one uint4 of halves.
__device__ __forceinline__ void gather_accum(float* acc, const __half* __restrict__ src,
                                             int c, float v, int lane) {
    const uint4* row = (const uint4*)(src + (size_t)c * NH);
    uint4 pv = __ldg(row + lane);
    const __half2* h = (const __half2*)&pv;
    float2 f0 = __half22float2(h[0]);
    float2 f1 = __half22float2(h[1]);
    float2 f2 = __half22float2(h[2]);
    float2 f3 = __half22float2(h[3]);
    acc[0] += v * f0.x; acc[1] += v * f0.y;
    acc[2] += v * f1.x; acc[3] += v * f1.y;
    acc[4] += v * f2.x; acc[5] += v * f2.y;
    acc[6] += v * f3.x; acc[7] += v * f3.y;
}

template <int NSRC>
__device__ __forceinline__ void spmm_accum(float* acc, int w, int lane,
                                           const __half* __restrict__ s0, int sel0,
                                           const __half* __restrict__ s1, int sel1,
                                           const __half* __restrict__ s2, int sel2) {
    const __half* srcs[3] = {s0, s1, s2};
    const int sels[3] = {sel0, sel1, sel2};
#pragma unroll
    for (int s = 0; s < NSRC; s++) {
        int adj = g_adj_idx[sels[s]];
        const int* rp = g_rowptr + adj * (NNODES + 1);
        int beg = __ldg(rp + w), end = __ldg(rp + w + 1);
        const int2* ed = g_edge + (size_t)adj * NEDGE;
        const __half* src = srcs[s];
        int2 e0 = make_int2(0, 0);
        if (beg < end) e0 = __ldg(ed + beg);
        for (int e = beg; e < end; e++) {
            int2 en = make_int2(0, 0);
            if (e + 1 < end) en = __ldg(ed + e + 1);
            gather_accum(acc, src, e0.x, __int_as_float(e0.y), lane);
            e0 = en;
        }
    }
}

template <int NSRC>
__global__ __launch_bounds__(256) void spmm_kernel(const __half* __restrict__ s0, int sel0,
                                                   const __half* __restrict__ s1, int sel1,
                                                   const __half* __restrict__ s2, int sel2,
                                                   __half* __restrict__ dst) {
    int w = (blockIdx.x * blockDim.x + threadIdx.x) >> 5;
    int lane = threadIdx.x & 31;
    if (w >= NNODES) return;
    float acc[8];
#pragma unroll
    for (int i = 0; i < 8; i++) acc[i] = 0.f;
    spmm_accum<NSRC>(acc, w, lane, s0, sel0, s1, sel1, s2, sel2);
    // pack 8 fp32 -> 4 half2 -> uint4, one 16B store per lane
    uint4 pk;
    half2* ph = (half2*)&pk;
    ph[0] = __floats2half2_rn(acc[0], acc[1]);
    ph[1] = __floats2half2_rn(acc[2], acc[3]);
    ph[2] = __floats2half2_rn(acc[4], acc[5]);
    ph[3] = __floats2half2_rn(acc[6], acc[7]);
    ((uint4*)(dst + (size_t)w * NH))[lane] = pk;
}

// ---------------- fused step-3 SpMM + LayerNorm + exact GELU -------------
__global__ __launch_bounds__(256) void spmm_ln_gelu_kernel(
    const __half* __restrict__ s0, int sel0,
    const __half* __restrict__ s1, int sel1,
    const __half* __restrict__ s2, int sel2,
    const float* __restrict__ gamma, const float* __restrict__ beta,
    float* __restrict__ out) {
    int w = (blockIdx.x * blockDim.x + threadIdx.x) >> 5;
    int lane = threadIdx.x & 31;
    if (w >= NNODES) return;
    float acc[8];
#pragma unroll
    for (int i = 0; i < 8; i++) acc[i] = 0.f;
    spmm_accum<3>(acc, w, lane, s0, sel0, s1, sel1, s2, sel2);

    float sum = 0.f, sq = 0.f;
#pragma unroll
    for (int i = 0; i < 8; i++) { sum += acc[i]; sq += acc[i] * acc[i]; }
#pragma unroll
    for (int off = 16; off >= 1; off >>= 1) {
        sum += __shfl_xor_sync(0xFFFFFFFFu, sum, off);
        sq  += __shfl_xor_sync(0xFFFFFFFFu, sq, off);
    }
    float mean = sum * (1.f / NH);
    float var = sq * (1.f / NH) - mean * mean;
    float inv = rsqrtf(var + LN_EPS);

    // lane owns cols lane*8 .. lane*8+7
    const float4* g4 = (const float4*)gamma;
    const float4* b4 = (const float4*)beta;
    float4 ga = __ldg(g4 + lane * 2), gb = __ldg(g4 + lane * 2 + 1);
    float4 ba = __ldg(b4 + lane * 2), bb = __ldg(b4 + lane * 2 + 1);
    float gs[8] = {ga.x, ga.y, ga.z, ga.w, gb.x, gb.y, gb.z, gb.w};
    float bs[8] = {ba.x, ba.y, ba.z, ba.w, bb.x, bb.y, bb.z, bb.w};
    float r[8];
#pragma unroll
    for (int i = 0; i < 8; i++) {
        float y = (acc[i] - mean) * inv * gs[i] + bs[i];
        r[i] = 0.5f * y * (1.f + erff(y * 0.70710678118654752f));
    }
    float4* o4 = (float4*)(out + (size_t)w * NH);
    o4[lane * 2] = make_float4(r[0], r[1], r[2], r[3]);
    o4[lane * 2 + 1] = make_float4(r[4], r[5], r[6], r[7]);
}

// ---------------- launch ---------------------------------------------
extern "C" void kernel_launch(void* const* d_in, const int* in_sizes, int n_in,
                              void* d_out, int out_size) {
    const float* x    = (const float*)d_in[0];
    const int* rows   = (const int*)d_in[1];
    const int* cols   = (const int*)d_in[2];
    const float* vals = (const float*)d_in[3];
    const int* seqr   = (const int*)d_in[4];
    const int* resr   = (const int*)d_in[5];
    const float* W    = (const float*)d_in[6];
    const float* b    = (const float*)d_in[7];
    const float* gamma = (const float*)d_in[8];
    const float* beta  = (const float*)d_in[9];
    float* out = (float*)d_out;

    static __half *s0p = nullptr, *s1p = nullptr, *s2p = nullptr;
    static cudaStream_t st2;
    static cudaEvent_t evFork, evJoin;
    if (!s0p) {
        cudaGetSymbolAddress((void**)&s0p, g_state0);
        cudaGetSymbolAddress((void**)&s1p, g_state1);
        cudaGetSymbolAddress((void**)&s2p, g_state2);
        cudaStreamCreateWithFlags(&st2, cudaStreamNonBlocking);
        cudaEventCreateWithFlags(&evFork, cudaEventDisableTiming);
        cudaEventCreateWithFlags(&evJoin, cudaEventDisableTiming);
    }

    // fork: GEMM on st2 runs concurrently with the CSR build chain
    cudaEventRecord(evFork, 0);
    cudaStreamWaitEvent(st2, evFork, 0);
    gemm_tf32_kernel<<<dim3((NNODES + GBM - 1) / GBM, NH / GBN), 256, 0, st2>>>(x, W, b, s0p);
    cudaEventRecord(evJoin, st2);

    // CSR build on the main (captured) stream
    decode_idx_kernel<<<1, 1>>>(seqr, resr);
    zero_cnt_kernel<<<(NADJ * NNODES + 255) / 256, 256>>>();
    hist_kernel<<<(NADJ * NEDGE + 255) / 256, 256>>>(rows);
    scanA_kernel<<<NADJ * BLK_PER_ADJ, SCAN_B>>>();
    scanB_kernel<<<1, 512>>>();
    scanC_kernel<<<NADJ * BLK_PER_ADJ, SCAN_B>>>();
    scatter_kernel<<<(NADJ * NEDGE + 255) / 256, 256>>>(rows, cols, vals);

    // join: SpMM chain needs both GEMM output and CSR
    cudaStreamWaitEvent(0, evJoin, 0);

    const int spmm_blocks = (NNODES + 7) / 8;  // warp per row, 8 warps/block
    spmm_kernel<1><<<spmm_blocks, 256>>>(s0p, 0, nullptr, 0, nullptr, 0, s1p);
    spmm_kernel<2><<<spmm_blocks, 256>>>(s1p, 1, s0p, 3, nullptr, 0, s2p);
    spmm_ln_gelu_kernel<<<spmm_blocks, 256>>>(s2p, 2, s0p, 4, s1p, 5, gamma, beta, out);
}

// round 11
// speedup vs baseline: 1.0070x; 1.0070x over previous
#include <cuda_runtime.h>
#include <cuda_fp16.h>
#include <math.h>

#define NNODES 50000
#define NADJ   6
#define NEDGE  800000
#define NH     256
#define LN_EPS 1e-5f

#define SCAN_B 1024
#define BLK_PER_ADJ ((NNODES + SCAN_B - 1) / SCAN_B)   // 49

// ---------------- device scratch (no allocations allowed) ----------------
static __device__ __align__(16) __half g_state0[(size_t)NNODES * NH];
static __device__ __align__(16) __half g_state1[(size_t)NNODES * NH];
static __device__ __align__(16) __half g_state2[(size_t)NNODES * NH];
static __device__ int   g_cnt[NADJ * NNODES];
static __device__ int   g_rowptr[NADJ * (NNODES + 1)];
static __device__ int   g_cur[NADJ * NNODES];
static __device__ int   g_blksum[NADJ * BLK_PER_ADJ];
static __device__ __align__(16) int2 g_edge[(size_t)NADJ * NEDGE];  // {col, val bits}
static __device__ int   g_adj_idx[6];   // [seq0,seq1,seq2,res0,res1,res2]
static __device__ int   g_used[NADJ];

// ---------------- idx decode: int32 vs int64 autodetect -------------------
__global__ void decode_idx_kernel(const int* __restrict__ seq_raw,
                                  const int* __restrict__ res_raw) {
    if (threadIdx.x != 0 || blockIdx.x != 0) return;
    long long a[6];
    int b[6];
    bool v64 = true, v32 = true;
    const long long* s64 = (const long long*)seq_raw;
    const long long* r64 = (const long long*)res_raw;
#pragma unroll
    for (int i = 0; i < 3; i++) {
        long long t = s64[i]; a[i] = t;     if (t < 0 || t >= NADJ) v64 = false;
        long long u = r64[i]; a[3 + i] = u; if (u < 0 || u >= NADJ) v64 = false;
        int p = seq_raw[i]; b[i] = p;       if (p < 0 || p >= NADJ) v32 = false;
        int q = res_raw[i]; b[3 + i] = q;   if (q < 0 || q >= NADJ) v32 = false;
    }
    (void)v32;
#pragma unroll
    for (int i = 0; i < NADJ; i++) g_used[i] = 0;
#pragma unroll
    for (int i = 0; i < 6; i++) {
        int v = v64 ? (int)a[i] : b[i];
        g_adj_idx[i] = v;
        g_used[v] = 1;
    }
}

// ---------------- CSR build --------------------------------------------
__global__ void zero_cnt_kernel() {
    int i = blockIdx.x * blockDim.x + threadIdx.x;
    if (i < NADJ * NNODES) g_cnt[i] = 0;
}

__global__ void hist_kernel(const int* __restrict__ rows) {
    int i = blockIdx.x * blockDim.x + threadIdx.x;
    if (i >= NADJ * NEDGE) return;
    int adj = i / NEDGE;
    if (!g_used[adj]) return;
    int r = rows[i];
    atomicAdd(&g_cnt[adj * NNODES + r], 1);
}

__global__ __launch_bounds__(SCAN_B) void scanA_kernel() {
    __shared__ int s[SCAN_B];
    int bx = blockIdx.x;
    int adj = bx / BLK_PER_ADJ;
    int blk = bx % BLK_PER_ADJ;
    int t = threadIdx.x;
    int i = blk * SCAN_B + t;
    int v = (i < NNODES) ? g_cnt[adj * NNODES + i] : 0;
    s[t] = v;
    __syncthreads();
#pragma unroll
    for (int off = 1; off < SCAN_B; off <<= 1) {
        int u = (t >= off) ? s[t - off] : 0;
        __syncthreads();
        s[t] += u;
        __syncthreads();
    }
    if (i < NNODES) g_cnt[adj * NNODES + i] = s[t] - v;
    if (t == SCAN_B - 1) g_blksum[adj * BLK_PER_ADJ + blk] = s[t];
}

__global__ __launch_bounds__(512) void scanB_kernel() {
    __shared__ int sb[NADJ * BLK_PER_ADJ];
    int t = threadIdx.x;
    for (int i = t; i < NADJ * BLK_PER_ADJ; i += blockDim.x) sb[i] = g_blksum[i];
    __syncthreads();
    if (t < NADJ) {
        int run = 0;
        for (int k = 0; k < BLK_PER_ADJ; k++) {
            int v = sb[t * BLK_PER_ADJ + k];
            sb[t * BLK_PER_ADJ + k] = run;
            run += v;
        }
        g_rowptr[t * (NNODES + 1) + NNODES] = run;
    }
    __syncthreads();
    for (int i = t; i < NADJ * BLK_PER_ADJ; i += blockDim.x) g_blksum[i] = sb[i];
}

__global__ __launch_bounds__(SCAN_B) void scanC_kernel() {
    int bx = blockIdx.x;
    int adj = bx / BLK_PER_ADJ;
    int blk = bx % BLK_PER_ADJ;
    int t = threadIdx.x;
    int i = blk * SCAN_B + t;
    if (i >= NNODES) return;
    int val = g_cnt[adj * NNODES + i] + g_blksum[adj * BLK_PER_ADJ + blk];
    g_rowptr[adj * (NNODES + 1) + i] = val;
    g_cur[adj * NNODES + i] = val;
}

__global__ void scatter_kernel(const int* __restrict__ rows,
                               const int* __restrict__ cols,
                               const float* __restrict__ vals) {
    int i = blockIdx.x * blockDim.x + threadIdx.x;
    if (i >= NADJ * NEDGE) return;
    int adj = i / NEDGE;
    if (!g_used[adj]) return;
    int r = rows[i];
    int pos = atomicAdd(&g_cur[adj * NNODES + r], 1);
    g_edge[(size_t)adj * NEDGE + pos] = make_int2(cols[i], __float_as_int(vals[i]));
}

// ---------------- TF32 split tensor-core GEMM, fp16 output ----------------
#define GBM 128
#define GBN 128
#define GBK 16
#define SPAD 20

__device__ __forceinline__ float f2tf32(float x) {
    float r;
    asm("cvt.rna.tf32.f32 %0, %1;" : "=f"(r) : "f"(x));
    return r;
}

__device__ __forceinline__ void mma_tf32(float* d, const float* a, float b0, float b1) {
    asm volatile(
        "mma.sync.aligned.m16n8k8.row.col.f32.tf32.tf32.f32 "
        "{%0,%1,%2,%3}, {%4,%5,%6,%7}, {%8,%9}, {%0,%1,%2,%3};"
        : "+f"(d[0]), "+f"(d[1]), "+f"(d[2]), "+f"(d[3])
        : "r"(__float_as_uint(a[0])), "r"(__float_as_uint(a[1])),
          "r"(__float_as_uint(a[2])), "r"(__float_as_uint(a[3])),
          "r"(__float_as_uint(b0)), "r"(__float_as_uint(b1)));
}

__global__ __launch_bounds__(256) void gemm_tf32_kernel(
    const float* __restrict__ A, const float* __restrict__ W,
    const float* __restrict__ bias, __half* __restrict__ C) {
    __shared__ float As_hi[GBM][SPAD];
    __shared__ float As_lo[GBM][SPAD];
    __shared__ float Bs_hi[GBN][SPAD];
    __shared__ float Bs_lo[GBN][SPAD];

    int t = threadIdx.x;
    int m0 = blockIdx.x * GBM;
    int n0 = blockIdx.y * GBN;
    int ws = t >> 5, lane = t & 31;
    int wm = ws & 3, wn = ws >> 2;
    int g = lane >> 2, t4 = lane & 3;

    float acc[2][8][4];
#pragma unroll
    for (int i = 0; i < 2; i++)
#pragma unroll
        for (int j = 0; j < 8; j++)
#pragma unroll
            for (int q = 0; q < 4; q++) acc[i][j][q] = 0.f;

    for (int k0 = 0; k0 < NH; k0 += GBK) {
#pragma unroll
        for (int L = 0; L < 2; L++) {
            int f = t + L * 256;
            int m = f >> 2, c4 = f & 3;
            int gm = m0 + m;
            float4 v = make_float4(0.f, 0.f, 0.f, 0.f);
            if (gm < NNODES)
                v = *(const float4*)(A + (size_t)gm * NH + k0 + c4 * 4);
            float4 h, l;
            h.x = f2tf32(v.x); l.x = f2tf32(v.x - h.x);
            h.y = f2tf32(v.y); l.y = f2tf32(v.y - h.y);
            h.z = f2tf32(v.z); l.z = f2tf32(v.z - h.z);
            h.w = f2tf32(v.w); l.w = f2tf32(v.w - h.w);
            *(float4*)&As_hi[m][c4 * 4] = h;
            *(float4*)&As_lo[m][c4 * 4] = l;
        }
#pragma unroll
        for (int L = 0; L < 2; L++) {
            int f = t + L * 256;
            int n = f >> 2, c4 = f & 3;
            float4 v = *(const float4*)(W + (size_t)(n0 + n) * NH + k0 + c4 * 4);
            float4 h, l;
            h.x = f2tf32(v.x); l.x = f2tf32(v.x - h.x);
            h.y = f2tf32(v.y); l.y = f2tf32(v.y - h.y);
            h.z = f2tf32(v.z); l.z = f2tf32(v.z - h.z);
            h.w = f2tf32(v.w); l.w = f2tf32(v.w - h.w);
            *(float4*)&Bs_hi[n][c4 * 4] = h;
            *(float4*)&Bs_lo[n][c4 * 4] = l;
        }
        __syncthreads();

#pragma unroll
        for (int k8 = 0; k8 < GBK / 8; k8++) {
            int kb = k8 * 8;
            float ah[2][4], al[2][4];
#pragma unroll
            for (int i = 0; i < 2; i++) {
                int mr = wm * 32 + i * 16;
                ah[i][0] = As_hi[mr + g][kb + t4];
                ah[i][1] = As_hi[mr + g + 8][kb + t4];
                ah[i][2] = As_hi[mr + g][kb + t4 + 4];
                ah[i][3] = As_hi[mr + g + 8][kb + t4 + 4];
                al[i][0] = As_lo[mr + g][kb + t4];
                al[i][1] = As_lo[mr + g + 8][kb + t4];
                al[i][2] = As_lo[mr + g][kb + t4 + 4];
                al[i][3] = As_lo[mr + g + 8][kb + t4 + 4];
            }
#pragma unroll
            for (int j = 0; j < 8; j++) {
                int nb = wn * 64 + j * 8;
                float b0h = Bs_hi[nb + g][kb + t4];
                float b1h = Bs_hi[nb + g][kb + t4 + 4];
                float b0l = Bs_lo[nb + g][kb + t4];
                float b1l = Bs_lo[nb + g][kb + t4 + 4];
#pragma unroll
                for (int i = 0; i < 2; i++) {
                    mma_tf32(acc[i][j], ah[i], b0h, b1h);
                    mma_tf32(acc[i][j], ah[i], b0l, b1l);
                    mma_tf32(acc[i][j], al[i], b0h, b1h);
                }
            }
        }
        __syncthreads();
    }

    // epilogue: + bias, convert to fp16, store half2
#pragma unroll
    for (int j = 0; j < 8; j++) {
        int c = n0 + wn * 64 + j * 8 + 2 * t4;
        float bx = __ldg(bias + c);
        float by = __ldg(bias + c + 1);
#pragma unroll
        for (int i = 0; i < 2; i++) {
            int r0 = m0 + wm * 32 + i * 16 + g;
            if (r0 < NNODES) {
                *(half2*)(C + (size_t)r0 * NH + c) =
                    __floats2half2_rn(acc[i][j][0] + bx, acc[i][j][1] + by);
            }
            int r1 = r0 + 8;
            if (r1 < NNODES) {
                *(half2*)(C + (size_t)r1 * NH + c) =
                    __floats2half2_rn(acc[i][j][2] + bx, acc[i][j][3] + by);
            }
        }
    }
}

// ---------------- CSR SpMM: warp-per-row, fp16 gather, fp32 accum ---------
// Each lane owns 8 consecutive cols (lane*8 .. lane*8+7) = one uint4 of halves.
__device__ __forceinline__ void gather_accum(float* acc, const __half* __restrict__ src,
                                             int c, float v, int lane) {
    const uint4* row = (const uint4*)(src + (size_t)c * NH);
    uint4 pv = __ldg(row + lane);
    const __half2* h = (const __half2*)&pv;
    float2 f0 = __half22float2(h[0]);
    float2 f1 = __half22float2(h[1]);
    float2 f2 = __half22float2(h[2]);
    float2 f3 = __half22float2(h[3]);
    acc[0] += v * f0.x; acc[1] += v * f0.y;
    acc[2] += v * f1.x; acc[3] += v * f1.y;
    acc[4] += v * f2.x; acc[5] += v * f2.y;
    acc[6] += v * f3.x; acc[7] += v * f3.y;
}

template <int NSRC>
__device__ __forceinline__ void spmm_accum(float* acc, int w, int lane,
                                           const __half* __restrict__ s0, int sel0,
                                           const __half* __restrict__ s1, int sel1,
                                           const __half* __restrict__ s2, int sel2) {
    const __half* srcs[3] = {s0, s1, s2};
    const int sels[3] = {sel0, sel1, sel2};
#pragma unroll
    for (int s = 0; s < NSRC; s++) {
        int adj = g_adj_idx[sels[s]];
        const int* rp = g_rowptr + adj * (NNODES + 1);
        int beg = __ldg(rp + w), end = __ldg(rp + w + 1);
        const int2* ed = g_edge + (size_t)adj * NEDGE;
        const __half* src = srcs[s];
        int2 e0 = make_int2(0, 0);
        if (beg < end) e0 = __ldg(ed + beg);
        for (int e = beg; e < end; e++) {
            int2 en = make_int2(0, 0);
            if (e + 1 < end) en = __ldg(ed + e + 1);
            gather_accum(acc, src, e0.x, __int_as_float(e0.y), lane);
            e0 = en;
        }
    }
}

template <int NSRC>
__global__ __launch_bounds__(256) void spmm_kernel(const __half* __restrict__ s0, int sel0,
                                                   const __half* __restrict__ s1, int sel1,
                                                   const __half* __restrict__ s2, int sel2,
                                                   __half* __restrict__ dst) {
    int w = (blockIdx.x * blockDim.x + threadIdx.x) >> 5;
    int lane = threadIdx.x & 31;
    if (w >= NNODES) return;
    float acc[8];
#pragma unroll
    for (int i = 0; i < 8; i++) acc[i] = 0.f;
    spmm_accum<NSRC>(acc, w, lane, s0, sel0, s1, sel1, s2, sel2);
    // pack 8 fp32 -> 4 half2 -> uint4, one 16B store per lane
    uint4 pk;
    half2* ph = (half2*)&pk;
    ph[0] = __floats2half2_rn(acc[0], acc[1]);
    ph[1] = __floats2half2_rn(acc[2], acc[3]);
    ph[2] = __floats2half2_rn(acc[4], acc[5]);
    ph[3] = __floats2half2_rn(acc[6], acc[7]);
    ((uint4*)(dst + (size_t)w * NH))[lane] = pk;
}

// ---------------- fused step-3 SpMM + LayerNorm + exact GELU -------------
__global__ __launch_bounds__(256) void spmm_ln_gelu_kernel(
    const __half* __restrict__ s0, int sel0,
    const __half* __restrict__ s1, int sel1,
    const __half* __restrict__ s2, int sel2,
    const float* __restrict__ gamma, const float* __restrict__ beta,
    float* __restrict__ out) {
    int w = (blockIdx.x * blockDim.x + threadIdx.x) >> 5;
    int lane = threadIdx.x & 31;
    if (w >= NNODES) return;
    float acc[8];
#pragma unroll
    for (int i = 0; i < 8; i++) acc[i] = 0.f;
    spmm_accum<3>(acc, w, lane, s0, sel0, s1, sel1, s2, sel2);

    float sum = 0.f, sq = 0.f;
#pragma unroll
    for (int i = 0; i < 8; i++) { sum += acc[i]; sq += acc[i] * acc[i]; }
#pragma unroll
    for (int off = 16; off >= 1; off >>= 1) {
        sum += __shfl_xor_sync(0xFFFFFFFFu, sum, off);
        sq  += __shfl_xor_sync(0xFFFFFFFFu, sq, off);
    }
    float mean = sum * (1.f / NH);
    float var = sq * (1.f / NH) - mean * mean;
    float inv = rsqrtf(var + LN_EPS);

    // lane owns cols lane*8 .. lane*8+7
    const float4* g4 = (const float4*)gamma;
    const float4* b4 = (const float4*)beta;
    float4 ga = __ldg(g4 + lane * 2), gb = __ldg(g4 + lane * 2 + 1);
    float4 ba = __ldg(b4 + lane * 2), bb = __ldg(b4 + lane * 2 + 1);
    float gs[8] = {ga.x, ga.y, ga.z, ga.w, gb.x, gb.y, gb.z, gb.w};
    float bs[8] = {ba.x, ba.y, ba.z, ba.w, bb.x, bb.y, bb.z, bb.w};
    float r[8];
#pragma unroll
    for (int i = 0; i < 8; i++) {
        float y = (acc[i] - mean) * inv * gs[i] + bs[i];
        r[i] = 0.5f * y * (1.f + erff(y * 0.70710678118654752f));
    }
    float4* o4 = (float4*)(out + (size_t)w * NH);
    o4[lane * 2] = make_float4(r[0], r[1], r[2], r[3]);
    o4[lane * 2 + 1] = make_float4(r[4], r[5], r[6], r[7]);
}

// ---------------- launch ---------------------------------------------
extern "C" void kernel_launch(void* const* d_in, const int* in_sizes, int n_in,
                              void* d_out, int out_size) {
    const float* x    = (const float*)d_in[0];
    const int* rows   = (const int*)d_in[1];
    const int* cols   = (const int*)d_in[2];
    const float* vals = (const float*)d_in[3];
    const int* seqr   = (const int*)d_in[4];
    const int* resr   = (const int*)d_in[5];
    const float* W    = (const float*)d_in[6];
    const float* b    = (const float*)d_in[7];
    const float* gamma = (const float*)d_in[8];
    const float* beta  = (const float*)d_in[9];
    float* out = (float*)d_out;

    static __half *s0p = nullptr, *s1p = nullptr, *s2p = nullptr;
    static cudaStream_t st2;
    static cudaEvent_t evFork, evJoin;
    if (!s0p) {
        cudaGetSymbolAddress((void**)&s0p, g_state0);
        cudaGetSymbolAddress((void**)&s1p, g_state1);
        cudaGetSymbolAddress((void**)&s2p, g_state2);
        cudaStreamCreateWithFlags(&st2, cudaStreamNonBlocking);
        cudaEventCreateWithFlags(&evFork, cudaEventDisableTiming);
        cudaEventCreateWithFlags(&evJoin, cudaEventDisableTiming);
    }

    // fork: GEMM on st2 runs concurrently with the CSR build chain
    cudaEventRecord(evFork, 0);
    cudaStreamWaitEvent(st2, evFork, 0);
    gemm_tf32_kernel<<<dim3((NNODES + GBM - 1) / GBM, NH / GBN), 256, 0, st2>>>(x, W, b, s0p);
    cudaEventRecord(evJoin, st2);

    // CSR build on the main (captured) stream
    decode_idx_kernel<<<1, 1>>>(seqr, resr);
    zero_cnt_kernel<<<(NADJ * NNODES + 255) / 256, 256>>>();
    hist_kernel<<<(NADJ * NEDGE + 255) / 256, 256>>>(rows);
    scanA_kernel<<<NADJ * BLK_PER_ADJ, SCAN_B>>>();
    scanB_kernel<<<1, 512>>>();
    scanC_kernel<<<NADJ * BLK_PER_ADJ, SCAN_B>>>();
    scatter_kernel<<<(NADJ * NEDGE + 255) / 256, 256>>>(rows, cols, vals);

    // join: SpMM chain needs both GEMM output and CSR
    cudaStreamWaitEvent(0, evJoin, 0);

    const int spmm_blocks = (NNODES + 7) / 8;  // warp per row, 8 warps/block
    spmm_kernel<1><<<spmm_blocks, 256>>>(s0p, 0, nullptr, 0, nullptr, 0, s1p);
    spmm_kernel<2><<<spmm_blocks, 256>>>(s1p, 1, s0p, 3, nullptr, 0, s2p);
    spmm_ln_gelu_kernel<<<spmm_blocks, 256>>>(s2p, 2, s0p, 4, s1p, 5, gamma, beta, out);
}

// round 12
// speedup vs baseline: 1.0082x; 1.0013x over previous
#include <cuda_runtime.h>
#include <cuda_fp16.h>
#include <math.h>

#define NNODES 50000
#define NADJ   6
#define NEDGE  800000
#define NH     256
#define LN_EPS 1e-5f

#define SCAN_B 1024
#define BLK_PER_ADJ ((NNODES + SCAN_B - 1) / SCAN_B)   // 49

// ---------------- device scratch (no allocations allowed) ----------------
static __device__ __align__(16) __half g_state0[(size_t)NNODES * NH];
static __device__ __align__(16) __half g_state1[(size_t)NNODES * NH];
static __device__ __align__(16) __half g_state2[(size_t)NNODES * NH];
static __device__ int   g_cnt[NADJ * NNODES];
static __device__ int   g_rowptr[NADJ * (NNODES + 1)];
static __device__ int   g_cur[NADJ * NNODES];
static __device__ int   g_blksum[NADJ * BLK_PER_ADJ];
static __device__ __align__(16) int2 g_edge[(size_t)NADJ * NEDGE];  // {col, val bits}
static __device__ int   g_adj_idx[6];   // [seq0,seq1,seq2,res0,res1,res2]
static __device__ int   g_used[NADJ];

// ---------------- idx decode: int32 vs int64 autodetect -------------------
__global__ void decode_idx_kernel(const int* __restrict__ seq_raw,
                                  const int* __restrict__ res_raw) {
    if (threadIdx.x != 0 || blockIdx.x != 0) return;
    long long a[6];
    int b[6];
    bool v64 = true, v32 = true;
    const long long* s64 = (const long long*)seq_raw;
    const long long* r64 = (const long long*)res_raw;
#pragma unroll
    for (int i = 0; i < 3; i++) {
        long long t = s64[i]; a[i] = t;     if (t < 0 || t >= NADJ) v64 = false;
        long long u = r64[i]; a[3 + i] = u; if (u < 0 || u >= NADJ) v64 = false;
        int p = seq_raw[i]; b[i] = p;       if (p < 0 || p >= NADJ) v32 = false;
        int q = res_raw[i]; b[3 + i] = q;   if (q < 0 || q >= NADJ) v32 = false;
    }
    (void)v32;
#pragma unroll
    for (int i = 0; i < NADJ; i++) g_used[i] = 0;
#pragma unroll
    for (int i = 0; i < 6; i++) {
        int v = v64 ? (int)a[i] : b[i];
        g_adj_idx[i] = v;
        g_used[v] = 1;
    }
}

// ---------------- CSR build --------------------------------------------
__global__ void zero_cnt_kernel() {
    int i = blockIdx.x * blockDim.x + threadIdx.x;
    if (i < NADJ * NNODES) g_cnt[i] = 0;
}

__global__ void hist_kernel(const int* __restrict__ rows) {
    int i = blockIdx.x * blockDim.x + threadIdx.x;
    if (i >= NADJ * NEDGE) return;
    int adj = i / NEDGE;
    if (!g_used[adj]) return;
    int r = rows[i];
    atomicAdd(&g_cnt[adj * NNODES + r], 1);
}

__global__ __launch_bounds__(SCAN_B) void scanA_kernel() {
    __shared__ int s[SCAN_B];
    int bx = blockIdx.x;
    int adj = bx / BLK_PER_ADJ;
    int blk = bx % BLK_PER_ADJ;
    int t = threadIdx.x;
    int i = blk * SCAN_B + t;
    int v = (i < NNODES) ? g_cnt[adj * NNODES + i] : 0;
    s[t] = v;
    __syncthreads();
#pragma unroll
    for (int off = 1; off < SCAN_B; off <<= 1) {
        int u = (t >= off) ? s[t - off] : 0;
        __syncthreads();
        s[t] += u;
        __syncthreads();
    }
    if (i < NNODES) g_cnt[adj * NNODES + i] = s[t] - v;
    if (t == SCAN_B - 1) g_blksum[adj * BLK_PER_ADJ + blk] = s[t];
}

__global__ __launch_bounds__(512) void scanB_kernel() {
    __shared__ int sb[NADJ * BLK_PER_ADJ];
    int t = threadIdx.x;
    for (int i = t; i < NADJ * BLK_PER_ADJ; i += blockDim.x) sb[i] = g_blksum[i];
    __syncthreads();
    if (t < NADJ) {
        int run = 0;
        for (int k = 0; k < BLK_PER_ADJ; k++) {
            int v = sb[t * BLK_PER_ADJ + k];
            sb[t * BLK_PER_ADJ + k] = run;
            run += v;
        }
        g_rowptr[t * (NNODES + 1) + NNODES] = run;
    }
    __syncthreads();
    for (int i = t; i < NADJ * BLK_PER_ADJ; i += blockDim.x) g_blksum[i] = sb[i];
}

__global__ __launch_bounds__(SCAN_B) void scanC_kernel() {
    int bx = blockIdx.x;
    int adj = bx / BLK_PER_ADJ;
    int blk = bx % BLK_PER_ADJ;
    int t = threadIdx.x;
    int i = blk * SCAN_B + t;
    if (i >= NNODES) return;
    int val = g_cnt[adj * NNODES + i] + g_blksum[adj * BLK_PER_ADJ + blk];
    g_rowptr[adj * (NNODES + 1) + i] = val;
    g_cur[adj * NNODES + i] = val;
}

__global__ void scatter_kernel(const int* __restrict__ rows,
                               const int* __restrict__ cols,
                               const float* __restrict__ vals) {
    int i = blockIdx.x * blockDim.x + threadIdx.x;
    if (i >= NADJ * NEDGE) return;
    int adj = i / NEDGE;
    if (!g_used[adj]) return;
    int r = rows[i];
    int pos = atomicAdd(&g_cur[adj * NNODES + r], 1);
    g_edge[(size_t)adj * NEDGE + pos] = make_int2(cols[i], __float_as_int(vals[i]));
}

// ---------------- TF32 split tensor-core GEMM, fp16 output ----------------
#define GBM 128
#define GBN 128
#define GBK 16
#define SPAD 20

__device__ __forceinline__ float f2tf32(float x) {
    float r;
    asm("cvt.rna.tf32.f32 %0, %1;" : "=f"(r) : "f"(x));
    return r;
}

__device__ __forceinline__ void mma_tf32(float* d, const float* a, float b0, float b1) {
    asm volatile(
        "mma.sync.aligned.m16n8k8.row.col.f32.tf32.tf32.f32 "
        "{%0,%1,%2,%3}, {%4,%5,%6,%7}, {%8,%9}, {%0,%1,%2,%3};"
        : "+f"(d[0]), "+f"(d[1]), "+f"(d[2]), "+f"(d[3])
        : "r"(__float_as_uint(a[0])), "r"(__float_as_uint(a[1])),
          "r"(__float_as_uint(a[2])), "r"(__float_as_uint(a[3])),
          "r"(__float_as_uint(b0)), "r"(__float_as_uint(b1)));
}

__global__ __launch_bounds__(256) void gemm_tf32_kernel(
    const float* __restrict__ A, const float* __restrict__ W,
    const float* __restrict__ bias, __half* __restrict__ C) {
    __shared__ float As_hi[GBM][SPAD];
    __shared__ float As_lo[GBM][SPAD];
    __shared__ float Bs_hi[GBN][SPAD];
    __shared__ float Bs_lo[GBN][SPAD];

    int t = threadIdx.x;
    int m0 = blockIdx.x * GBM;
    int n0 = blockIdx.y * GBN;
    int ws = t >> 5, lane = t & 31;
    int wm = ws & 3, wn = ws >> 2;
    int g = lane >> 2, t4 = lane & 3;

    float acc[2][8][4];
#pragma unroll
    for (int i = 0; i < 2; i++)
#pragma unroll
        for (int j = 0; j < 8; j++)
#pragma unroll
            for (int q = 0; q < 4; q++) acc[i][j][q] = 0.f;

    for (int k0 = 0; k0 < NH; k0 += GBK) {
#pragma unroll
        for (int L = 0; L < 2; L++) {
            int f = t + L * 256;
            int m = f >> 2, c4 = f & 3;
            int gm = m0 + m;
            float4 v = make_float4(0.f, 0.f, 0.f, 0.f);
            if (gm < NNODES)
                v = *(const float4*)(A + (size_t)gm * NH + k0 + c4 * 4);
            float4 h, l;
            h.x = f2tf32(v.x); l.x = f2tf32(v.x - h.x);
            h.y = f2tf32(v.y); l.y = f2tf32(v.y - h.y);
            h.z = f2tf32(v.z); l.z = f2tf32(v.z - h.z);
            h.w = f2tf32(v.w); l.w = f2tf32(v.w - h.w);
            *(float4*)&As_hi[m][c4 * 4] = h;
            *(float4*)&As_lo[m][c4 * 4] = l;
        }
#pragma unroll
        for (int L = 0; L < 2; L++) {
            int f = t + L * 256;
            int n = f >> 2, c4 = f & 3;
            float4 v = *(const float4*)(W + (size_t)(n0 + n) * NH + k0 + c4 * 4);
            float4 h, l;
            h.x = f2tf32(v.x); l.x = f2tf32(v.x - h.x);
            h.y = f2tf32(v.y); l.y = f2tf32(v.y - h.y);
            h.z = f2tf32(v.z); l.z = f2tf32(v.z - h.z);
            h.w = f2tf32(v.w); l.w = f2tf32(v.w - h.w);
            *(float4*)&Bs_hi[n][c4 * 4] = h;
            *(float4*)&Bs_lo[n][c4 * 4] = l;
        }
        __syncthreads();

#pragma unroll
        for (int k8 = 0; k8 < GBK / 8; k8++) {
            int kb = k8 * 8;
            float ah[2][4], al[2][4];
#pragma unroll
            for (int i = 0; i < 2; i++) {
                int mr = wm * 32 + i * 16;
                ah[i][0] = As_hi[mr + g][kb + t4];
                ah[i][1] = As_hi[mr + g + 8][kb + t4];
                ah[i][2] = As_hi[mr + g][kb + t4 + 4];
                ah[i][3] = As_hi[mr + g + 8][kb + t4 + 4];
                al[i][0] = As_lo[mr + g][kb + t4];
                al[i][1] = As_lo[mr + g + 8][kb + t4];
                al[i][2] = As_lo[mr + g][kb + t4 + 4];
                al[i][3] = As_lo[mr + g + 8][kb + t4 + 4];
            }
#pragma unroll
            for (int j = 0; j < 8; j++) {
                int nb = wn * 64 + j * 8;
                float b0h = Bs_hi[nb + g][kb + t4];
                float b1h = Bs_hi[nb + g][kb + t4 + 4];
                float b0l = Bs_lo[nb + g][kb + t4];
                float b1l = Bs_lo[nb + g][kb + t4 + 4];
#pragma unroll
                for (int i = 0; i < 2; i++) {
                    mma_tf32(acc[i][j], ah[i], b0h, b1h);
                    mma_tf32(acc[i][j], ah[i], b0l, b1l);
                    mma_tf32(acc[i][j], al[i], b0h, b1h);
                }
            }
        }
        __syncthreads();
    }

    // epilogue: + bias, convert to fp16, store half2
#pragma unroll
    for (int j = 0; j < 8; j++) {
        int c = n0 + wn * 64 + j * 8 + 2 * t4;
        float bx = __ldg(bias + c);
        float by = __ldg(bias + c + 1);
#pragma unroll
        for (int i = 0; i < 2; i++) {
            int r0 = m0 + wm * 32 + i * 16 + g;
            if (r0 < NNODES) {
                *(half2*)(C + (size_t)r0 * NH + c) =
                    __floats2half2_rn(acc[i][j][0] + bx, acc[i][j][1] + by);
            }
            int r1 = r0 + 8;
            if (r1 < NNODES) {
                *(half2*)(C + (size_t)r1 * NH + c) =
                    __floats2half2_rn(acc[i][j][2] + bx, acc[i][j][3] + by);
            }
        }
    }
}

// ---------------- CSR SpMM: warp-per-row, fp16 gather, fp32 accum ---------
// Each lane owns 8 consecutive cols (lane*8 .. lane*8+7) = one uint4 of halves.
__device__ __forceinline__ void gather_accum(float* acc, const __half* __restrict__ src,
                                             int c, float v, int lane) {
    const uint4* row = (const uint4*)(src + (size_t)c * NH);
    uint4 pv = __ldg(row + lane);
    const __half2* h = (const __half2*)&pv;
    float2 f0 = __half22float2(h[0]);
    float2 f1 = __half22float2(h[1]);
    float2 f2 = __half22float2(h[2]);
    float2 f3 = __half22float2(h[3]);
    acc[0] += v * f0.x; acc[1] += v * f0.y;
    acc[2] += v * f1.x; acc[3] += v * f1.y;
    acc[4] += v * f2.x; acc[5] += v * f2.y;
    acc[6] += v * f3.x; acc[7] += v * f3.y;
}

template <int NSRC>
__device__ __forceinline__ void spmm_accum(float* acc, int w, int lane,
                                           const __half* __restrict__ s0, int sel0,
                                           const __half* __restrict__ s1, int sel1,
                                           const __half* __restrict__ s2, int sel2) {
    const __half* srcs[3] = {s0, s1, s2};
    const int sels[3] = {sel0, sel1, sel2};
#pragma unroll
    for (int s = 0; s < NSRC; s++) {
        int adj = g_adj_idx[sels[s]];
        const int* rp = g_rowptr + adj * (NNODES + 1);
        int beg = __ldg(rp + w), end = __ldg(rp + w + 1);
        const int2* ed = g_edge + (size_t)adj * NEDGE;
        const __half* src = srcs[s];
        int2 e0 = make_int2(0, 0);
        if (beg < end) e0 = __ldg(ed + beg);
        for (int e = beg; e < end; e++) {
            int2 en = make_int2(0, 0);
            if (e + 1 < end) en = __ldg(ed + e + 1);
            gather_accum(acc, src, e0.x, __int_as_float(e0.y), lane);
            e0 = en;
        }
    }
}

template <int NSRC>
__global__ __launch_bounds__(256) void spmm_kernel(const __half* __restrict__ s0, int sel0,
                                                   const __half* __restrict__ s1, int sel1,
                                                   const __half* __restrict__ s2, int sel2,
                                                   __half* __restrict__ dst) {
    int w = (blockIdx.x * blockDim.x + threadIdx.x) >> 5;
    int lane = threadIdx.x & 31;
    if (w >= NNODES) return;
    float acc[8];
#pragma unroll
    for (int i = 0; i < 8; i++) acc[i] = 0.f;
    spmm_accum<NSRC>(acc, w, lane, s0, sel0, s1, sel1, s2, sel2);
    // pack 8 fp32 -> 4 half2 -> uint4, one 16B store per lane
    uint4 pk;
    half2* ph = (half2*)&pk;
    ph[0] = __floats2half2_rn(acc[0], acc[1]);
    ph[1] = __floats2half2_rn(acc[2], acc[3]);
    ph[2] = __floats2half2_rn(acc[4], acc[5]);
    ph[3] = __floats2half2_rn(acc[6], acc[7]);
    ((uint4*)(dst + (size_t)w * NH))[lane] = pk;
}

// ---------------- fused step-3 SpMM + LayerNorm + exact GELU -------------
__global__ __launch_bounds__(256) void spmm_ln_gelu_kernel(
    const __half* __restrict__ s0, int sel0,
    const __half* __restrict__ s1, int sel1,
    const __half* __restrict__ s2, int sel2,
    const float* __restrict__ gamma, const float* __restrict__ beta,
    float* __restrict__ out) {
    int w = (blockIdx.x * blockDim.x + threadIdx.x) >> 5;
    int lane = threadIdx.x & 31;
    if (w >= NNODES) return;
    float acc[8];
#pragma unroll
    for (int i = 0; i < 8; i++) acc[i] = 0.f;
    spmm_accum<3>(acc, w, lane, s0, sel0, s1, sel1, s2, sel2);

    float sum = 0.f, sq = 0.f;
#pragma unroll
    for (int i = 0; i < 8; i++) { sum += acc[i]; sq += acc[i] * acc[i]; }
#pragma unroll
    for (int off = 16; off >= 1; off >>= 1) {
        sum += __shfl_xor_sync(0xFFFFFFFFu, sum, off);
        sq  += __shfl_xor_sync(0xFFFFFFFFu, sq, off);
    }
    float mean = sum * (1.f / NH);
    float var = sq * (1.f / NH) - mean * mean;
    float inv = rsqrtf(var + LN_EPS);

    // lane owns cols lane*8 .. lane*8+7
    const float4* g4 = (const float4*)gamma;
    const float4* b4 = (const float4*)beta;
    float4 ga = __ldg(g4 + lane * 2), gb = __ldg(g4 + lane * 2 + 1);
    float4 ba = __ldg(b4 + lane * 2), bb = __ldg(b4 + lane * 2 + 1);
    float gs[8] = {ga.x, ga.y, ga.z, ga.w, gb.x, gb.y, gb.z, gb.w};
    float bs[8] = {ba.x, ba.y, ba.z, ba.w, bb.x, bb.y, bb.z, bb.w};
    float r[8];
#pragma unroll
    for (int i = 0; i < 8; i++) {
        float y = (acc[i] - mean) * inv * gs[i] + bs[i];
        r[i] = 0.5f * y * (1.f + erff(y * 0.70710678118654752f));
    }
    float4* o4 = (float4*)(out + (size_t)w * NH);
    o4[lane * 2] = make_float4(r[0], r[1], r[2], r[3]);
    o4[lane * 2 + 1] = make_float4(r[4], r[5], r[6], r[7]);
}

// ---------------- launch ---------------------------------------------
extern "C" void kernel_launch(void* const* d_in, const int* in_sizes, int n_in,
                              void* d_out, int out_size) {
    const float* x    = (const float*)d_in[0];
    const int* rows   = (const int*)d_in[1];
    const int* cols   = (const int*)d_in[2];
    const float* vals = (const float*)d_in[3];
    const int* seqr   = (const int*)d_in[4];
    const int* resr   = (const int*)d_in[5];
    const float* W    = (const float*)d_in[6];
    const float* b    = (const float*)d_in[7];
    const float* gamma = (const float*)d_in[8];
    const float* beta  = (const float*)d_in[9];
    float* out = (float*)d_out;

    static __half *s0p = nullptr, *s1p = nullptr, *s2p = nullptr;
    static cudaStream_t st2;
    static cudaEvent_t evFork, evJoin;
    if (!s0p) {
        cudaGetSymbolAddress((void**)&s0p, g_state0);
        cudaGetSymbolAddress((void**)&s1p, g_state1);
        cudaGetSymbolAddress((void**)&s2p, g_state2);
        cudaStreamCreateWithFlags(&st2, cudaStreamNonBlocking);
        cudaEventCreateWithFlags(&evFork, cudaEventDisableTiming);
        cudaEventCreateWithFlags(&evJoin, cudaEventDisableTiming);
    }

    // fork: GEMM on st2 runs concurrently with the CSR build chain
    cudaEventRecord(evFork, 0);
    cudaStreamWaitEvent(st2, evFork, 0);
    gemm_tf32_kernel<<<dim3((NNODES + GBM - 1) / GBM, NH / GBN), 256, 0, st2>>>(x, W, b, s0p);
    cudaEventRecord(evJoin, st2);

    // CSR build on the main (captured) stream
    decode_idx_kernel<<<1, 1>>>(seqr, resr);
    zero_cnt_kernel<<<(NADJ * NNODES + 255) / 256, 256>>>();
    hist_kernel<<<(NADJ * NEDGE + 255) / 256, 256>>>(rows);
    scanA_kernel<<<NADJ * BLK_PER_ADJ, SCAN_B>>>();
    scanB_kernel<<<1, 512>>>();
    scanC_kernel<<<NADJ * BLK_PER_ADJ, SCAN_B>>>();
    scatter_kernel<<<(NADJ * NEDGE + 255) / 256, 256>>>(rows, cols, vals);

    // join: SpMM chain needs both GEMM output and CSR
    cudaStreamWaitEvent(0, evJoin, 0);

    const int spmm_blocks = (NNODES + 7) / 8;  // warp per row, 8 warps/block
    spmm_kernel<1><<<spmm_blocks, 256>>>(s0p, 0, nullptr, 0, nullptr, 0, s1p);
    spmm_kernel<2><<<spmm_blocks, 256>>>(s1p, 1, s0p, 3, nullptr, 0, s2p);
    spmm_ln_gelu_kernel<<<spmm_blocks, 256>>>(s2p, 2, s0p, 4, s1p, 5, gamma, beta, out);
}

// round 13
// speedup vs baseline: 1.0303x; 1.0219x over previous
#include <cuda_runtime.h>
#include <cuda_fp16.h>
#include <math.h>

#define NNODES 50000
#define NADJ   6
#define NEDGE  800000
#define NH     256
#define LN_EPS 1e-5f

#define SCAN_B 1024
#define BLK_PER_ADJ ((NNODES + SCAN_B - 1) / SCAN_B)   // 49

// ---------------- device scratch (no allocations allowed) ----------------
static __device__ __align__(16) __half g_state0[(size_t)NNODES * NH];
static __device__ __align__(16) __half g_state1[(size_t)NNODES * NH];
static __device__ __align__(16) __half g_state2[(size_t)NNODES * NH];
static __device__ __align__(16) __half g_t2a[(size_t)NNODES * NH];
static __device__ __align__(16) __half g_t3a[(size_t)NNODES * NH];
static __device__ __align__(16) __half g_t3b[(size_t)NNODES * NH];
static __device__ int   g_cnt[NADJ * NNODES];
static __device__ int   g_rowptr[NADJ * (NNODES + 1)];
static __device__ int   g_cur[NADJ * NNODES];
static __device__ int   g_blksum[NADJ * BLK_PER_ADJ];
static __device__ __align__(16) int2 g_edge[(size_t)NADJ * NEDGE];  // {col, val bits}
static __device__ int   g_adj_idx[6];   // [seq0,seq1,seq2,res0,res1,res2]
static __device__ int   g_used[NADJ];

// ---------------- idx decode: int32 vs int64 autodetect -------------------
__global__ void decode_idx_kernel(const int* __restrict__ seq_raw,
                                  const int* __restrict__ res_raw) {
    if (threadIdx.x != 0 || blockIdx.x != 0) return;
    long long a[6];
    int b[6];
    bool v64 = true, v32 = true;
    const long long* s64 = (const long long*)seq_raw;
    const long long* r64 = (const long long*)res_raw;
#pragma unroll
    for (int i = 0; i < 3; i++) {
        long long t = s64[i]; a[i] = t;     if (t < 0 || t >= NADJ) v64 = false;
        long long u = r64[i]; a[3 + i] = u; if (u < 0 || u >= NADJ) v64 = false;
        int p = seq_raw[i]; b[i] = p;       if (p < 0 || p >= NADJ) v32 = false;
        int q = res_raw[i]; b[3 + i] = q;   if (q < 0 || q >= NADJ) v32 = false;
    }
    (void)v32;
#pragma unroll
    for (int i = 0; i < NADJ; i++) g_used[i] = 0;
#pragma unroll
    for (int i = 0; i < 6; i++) {
        int v = v64 ? (int)a[i] : b[i];
        g_adj_idx[i] = v;
        g_used[v] = 1;
    }
}

// ---------------- CSR build --------------------------------------------
__global__ void zero_cnt_kernel() {
    int i = blockIdx.x * blockDim.x + threadIdx.x;
    if (i < NADJ * NNODES) g_cnt[i] = 0;
}

// 4 edges per thread (NEDGE % 4 == 0, so all 4 share an adjacency)
__global__ void hist_kernel(const int4* __restrict__ rows4) {
    int i = blockIdx.x * blockDim.x + threadIdx.x;
    if (i >= NADJ * NEDGE / 4) return;
    int adj = (i * 4) / NEDGE;
    if (!g_used[adj]) return;
    int4 r = __ldg(rows4 + i);
    int* cnt = g_cnt + adj * NNODES;
    atomicAdd(cnt + r.x, 1);
    atomicAdd(cnt + r.y, 1);
    atomicAdd(cnt + r.z, 1);
    atomicAdd(cnt + r.w, 1);
}

__global__ __launch_bounds__(SCAN_B) void scanA_kernel() {
    __shared__ int s[SCAN_B];
    int bx = blockIdx.x;
    int adj = bx / BLK_PER_ADJ;
    int blk = bx % BLK_PER_ADJ;
    int t = threadIdx.x;
    int i = blk * SCAN_B + t;
    int v = (i < NNODES) ? g_cnt[adj * NNODES + i] : 0;
    s[t] = v;
    __syncthreads();
#pragma unroll
    for (int off = 1; off < SCAN_B; off <<= 1) {
        int u = (t >= off) ? s[t - off] : 0;
        __syncthreads();
        s[t] += u;
        __syncthreads();
    }
    if (i < NNODES) g_cnt[adj * NNODES + i] = s[t] - v;
    if (t == SCAN_B - 1) g_blksum[adj * BLK_PER_ADJ + blk] = s[t];
}

__global__ __launch_bounds__(512) void scanB_kernel() {
    __shared__ int sb[NADJ * BLK_PER_ADJ];
    int t = threadIdx.x;
    for (int i = t; i < NADJ * BLK_PER_ADJ; i += blockDim.x) sb[i] = g_blksum[i];
    __syncthreads();
    if (t < NADJ) {
        int run = 0;
        for (int k = 0; k < BLK_PER_ADJ; k++) {
            int v = sb[t * BLK_PER_ADJ + k];
            sb[t * BLK_PER_ADJ + k] = run;
            run += v;
        }
        g_rowptr[t * (NNODES + 1) + NNODES] = run;
    }
    __syncthreads();
    for (int i = t; i < NADJ * BLK_PER_ADJ; i += blockDim.x) g_blksum[i] = sb[i];
}

__global__ __launch_bounds__(SCAN_B) void scanC_kernel() {
    int bx = blockIdx.x;
    int adj = bx / BLK_PER_ADJ;
    int blk = bx % BLK_PER_ADJ;
    int t = threadIdx.x;
    int i = blk * SCAN_B + t;
    if (i >= NNODES) return;
    int val = g_cnt[adj * NNODES + i] + g_blksum[adj * BLK_PER_ADJ + blk];
    g_rowptr[adj * (NNODES + 1) + i] = val;
    g_cur[adj * NNODES + i] = val;
}

// 4 edges per thread
__global__ void scatter_kernel(const int4* __restrict__ rows4,
                               const int4* __restrict__ cols4,
                               const float4* __restrict__ vals4) {
    int i = blockIdx.x * blockDim.x + threadIdx.x;
    if (i >= NADJ * NEDGE / 4) return;
    int adj = (i * 4) / NEDGE;
    if (!g_used[adj]) return;
    int4 r = __ldg(rows4 + i);
    int4 c = __ldg(cols4 + i);
    float4 v = __ldg(vals4 + i);
    int* cur = g_cur + adj * NNODES;
    int2* ed = (int2*)(g_edge + (size_t)adj * NEDGE);
    int p0 = atomicAdd(cur + r.x, 1);
    ed[p0] = make_int2(c.x, __float_as_int(v.x));
    int p1 = atomicAdd(cur + r.y, 1);
    ed[p1] = make_int2(c.y, __float_as_int(v.y));
    int p2 = atomicAdd(cur + r.z, 1);
    ed[p2] = make_int2(c.z, __float_as_int(v.z));
    int p3 = atomicAdd(cur + r.w, 1);
    ed[p3] = make_int2(c.w, __float_as_int(v.w));
}

// ---------------- TF32 split tensor-core GEMM, fp16 output ----------------
#define GBM 128
#define GBN 128
#define GBK 16
#define SPAD 20

__device__ __forceinline__ float f2tf32(float x) {
    float r;
    asm("cvt.rna.tf32.f32 %0, %1;" : "=f"(r) : "f"(x));
    return r;
}

__device__ __forceinline__ void mma_tf32(float* d, const float* a, float b0, float b1) {
    asm volatile(
        "mma.sync.aligned.m16n8k8.row.col.f32.tf32.tf32.f32 "
        "{%0,%1,%2,%3}, {%4,%5,%6,%7}, {%8,%9}, {%0,%1,%2,%3};"
        : "+f"(d[0]), "+f"(d[1]), "+f"(d[2]), "+f"(d[3])
        : "r"(__float_as_uint(a[0])), "r"(__float_as_uint(a[1])),
          "r"(__float_as_uint(a[2])), "r"(__float_as_uint(a[3])),
          "r"(__float_as_uint(b0)), "r"(__float_as_uint(b1)));
}

__global__ __launch_bounds__(256) void gemm_tf32_kernel(
    const float* __restrict__ A, const float* __restrict__ W,
    const float* __restrict__ bias, __half* __restrict__ C) {
    __shared__ float As_hi[GBM][SPAD];
    __shared__ float As_lo[GBM][SPAD];
    __shared__ float Bs_hi[GBN][SPAD];
    __shared__ float Bs_lo[GBN][SPAD];

    int t = threadIdx.x;
    int m0 = blockIdx.x * GBM;
    int n0 = blockIdx.y * GBN;
    int ws = t >> 5, lane = t & 31;
    int wm = ws & 3, wn = ws >> 2;
    int g = lane >> 2, t4 = lane & 3;

    float acc[2][8][4];
#pragma unroll
    for (int i = 0; i < 2; i++)
#pragma unroll
        for (int j = 0; j < 8; j++)
#pragma unroll
            for (int q = 0; q < 4; q++) acc[i][j][q] = 0.f;

    for (int k0 = 0; k0 < NH; k0 += GBK) {
#pragma unroll
        for (int L = 0; L < 2; L++) {
            int f = t + L * 256;
            int m = f >> 2, c4 = f & 3;
            int gm = m0 + m;
            float4 v = make_float4(0.f, 0.f, 0.f, 0.f);
            if (gm < NNODES)
                v = *(const float4*)(A + (size_t)gm * NH + k0 + c4 * 4);
            float4 h, l;
            h.x = f2tf32(v.x); l.x = f2tf32(v.x - h.x);
            h.y = f2tf32(v.y); l.y = f2tf32(v.y - h.y);
            h.z = f2tf32(v.z); l.z = f2tf32(v.z - h.z);
            h.w = f2tf32(v.w); l.w = f2tf32(v.w - h.w);
            *(float4*)&As_hi[m][c4 * 4] = h;
            *(float4*)&As_lo[m][c4 * 4] = l;
        }
#pragma unroll
        for (int L = 0; L < 2; L++) {
            int f = t + L * 256;
            int n = f >> 2, c4 = f & 3;
            float4 v = *(const float4*)(W + (size_t)(n0 + n) * NH + k0 + c4 * 4);
            float4 h, l;
            h.x = f2tf32(v.x); l.x = f2tf32(v.x - h.x);
            h.y = f2tf32(v.y); l.y = f2tf32(v.y - h.y);
            h.z = f2tf32(v.z); l.z = f2tf32(v.z - h.z);
            h.w = f2tf32(v.w); l.w = f2tf32(v.w - h.w);
            *(float4*)&Bs_hi[n][c4 * 4] = h;
            *(float4*)&Bs_lo[n][c4 * 4] = l;
        }
        __syncthreads();

#pragma unroll
        for (int k8 = 0; k8 < GBK / 8; k8++) {
            int kb = k8 * 8;
            float ah[2][4], al[2][4];
#pragma unroll
            for (int i = 0; i < 2; i++) {
                int mr = wm * 32 + i * 16;
                ah[i][0] = As_hi[mr + g][kb + t4];
                ah[i][1] = As_hi[mr + g + 8][kb + t4];
                ah[i][2] = As_hi[mr + g][kb + t4 + 4];
                ah[i][3] = As_hi[mr + g + 8][kb + t4 + 4];
                al[i][0] = As_lo[mr + g][kb + t4];
                al[i][1] = As_lo[mr + g + 8][kb + t4];
                al[i][2] = As_lo[mr + g][kb + t4 + 4];
                al[i][3] = As_lo[mr + g + 8][kb + t4 + 4];
            }
#pragma unroll
            for (int j = 0; j < 8; j++) {
                int nb = wn * 64 + j * 8;
                float b0h = Bs_hi[nb + g][kb + t4];
                float b1h = Bs_hi[nb + g][kb + t4 + 4];
                float b0l = Bs_lo[nb + g][kb + t4];
                float b1l = Bs_lo[nb + g][kb + t4 + 4];
#pragma unroll
                for (int i = 0; i < 2; i++) {
                    mma_tf32(acc[i][j], ah[i], b0h, b1h);
                    mma_tf32(acc[i][j], ah[i], b0l, b1l);
                    mma_tf32(acc[i][j], al[i], b0h, b1h);
                }
            }
        }
        __syncthreads();
    }

#pragma unroll
    for (int j = 0; j < 8; j++) {
        int c = n0 + wn * 64 + j * 8 + 2 * t4;
        float bx = __ldg(bias + c);
        float by = __ldg(bias + c + 1);
#pragma unroll
        for (int i = 0; i < 2; i++) {
            int r0 = m0 + wm * 32 + i * 16 + g;
            if (r0 < NNODES) {
                *(half2*)(C + (size_t)r0 * NH + c) =
                    __floats2half2_rn(acc[i][j][0] + bx, acc[i][j][1] + by);
            }
            int r1 = r0 + 8;
            if (r1 < NNODES) {
                *(half2*)(C + (size_t)r1 * NH + c) =
                    __floats2half2_rn(acc[i][j][2] + bx, acc[i][j][3] + by);
            }
        }
    }
}

// ---------------- CSR SpMM primitives -------------------------------------
// Each lane owns 8 consecutive cols (lane*8 .. lane*8+7) = one uint4 of halves.
__device__ __forceinline__ void gather_accum(float* acc, const __half* __restrict__ src,
                                             int c, float v, int lane) {
    const uint4* row = (const uint4*)(src + (size_t)c * NH);
    uint4 pv = __ldg(row + lane);
    const __half2* h = (const __half2*)&pv;
    float2 f0 = __half22float2(h[0]);
    float2 f1 = __half22float2(h[1]);
    float2 f2 = __half22float2(h[2]);
    float2 f3 = __half22float2(h[3]);
    acc[0] += v * f0.x; acc[1] += v * f0.y;
    acc[2] += v * f1.x; acc[3] += v * f1.y;
    acc[4] += v * f2.x; acc[5] += v * f2.y;
    acc[6] += v * f3.x; acc[7] += v * f3.y;
}

__device__ __forceinline__ void spmm_row(float* acc, int w, int lane,
                                         const __half* __restrict__ src, int selpos) {
    int adj = g_adj_idx[selpos];
    const int* rp = g_rowptr + adj * (NNODES + 1);
    int beg = __ldg(rp + w), end = __ldg(rp + w + 1);
    const int2* ed = g_edge + (size_t)adj * NEDGE;
    int2 e0 = make_int2(0, 0);
    if (beg < end) e0 = __ldg(ed + beg);
    for (int e = beg; e < end; e++) {
        int2 en = make_int2(0, 0);
        if (e + 1 < end) en = __ldg(ed + e + 1);
        gather_accum(acc, src, e0.x, __int_as_float(e0.y), lane);
        e0 = en;
    }
}

__device__ __forceinline__ void add_dense(float* acc, const __half* __restrict__ a,
                                          int w, int lane) {
    uint4 pv = __ldg((const uint4*)(a + (size_t)w * NH) + lane);
    const __half2* h = (const __half2*)&pv;
    float2 f0 = __half22float2(h[0]);
    float2 f1 = __half22float2(h[1]);
    float2 f2 = __half22float2(h[2]);
    float2 f3 = __half22float2(h[3]);
    acc[0] += f0.x; acc[1] += f0.y;
    acc[2] += f1.x; acc[3] += f1.y;
    acc[4] += f2.x; acc[5] += f2.y;
    acc[6] += f3.x; acc[7] += f3.y;
}

__device__ __forceinline__ void store_row_h(float* acc, __half* __restrict__ dst,
                                            int w, int lane) {
    uint4 pk;
    half2* ph = (half2*)&pk;
    ph[0] = __floats2half2_rn(acc[0], acc[1]);
    ph[1] = __floats2half2_rn(acc[2], acc[3]);
    ph[2] = __floats2half2_rn(acc[4], acc[5]);
    ph[3] = __floats2half2_rn(acc[6], acc[7]);
    ((uint4*)(dst + (size_t)w * NH))[lane] = pk;
}

// dst = adj[sel] @ src   (+ optional dense addend)
template <int NADD>
__global__ __launch_bounds__(256) void spmm_kernel(const __half* __restrict__ src, int sel,
                                                   const __half* __restrict__ add0,
                                                   __half* __restrict__ dst) {
    int w = (blockIdx.x * blockDim.x + threadIdx.x) >> 5;
    int lane = threadIdx.x & 31;
    if (w >= NNODES) return;
    float acc[8];
#pragma unroll
    for (int i = 0; i < 8; i++) acc[i] = 0.f;
    spmm_row(acc, w, lane, src, sel);
    if (NADD >= 1) add_dense(acc, add0, w, lane);
    store_row_h(acc, dst, w, lane);
}

// out = GELU(LN(adj[sel] @ src + t3a + t3b))
__global__ __launch_bounds__(256) void spmm_ln_gelu_kernel(
    const __half* __restrict__ src, int sel,
    const __half* __restrict__ add0, const __half* __restrict__ add1,
    const float* __restrict__ gamma, const float* __restrict__ beta,
    float* __restrict__ out) {
    int w = (blockIdx.x * blockDim.x + threadIdx.x) >> 5;
    int lane = threadIdx.x & 31;
    if (w >= NNODES) return;
    float acc[8];
#pragma unroll
    for (int i = 0; i < 8; i++) acc[i] = 0.f;
    spmm_row(acc, w, lane, src, sel);
    add_dense(acc, add0, w, lane);
    add_dense(acc, add1, w, lane);

    float sum = 0.f, sq = 0.f;
#pragma unroll
    for (int i = 0; i < 8; i++) { sum += acc[i]; sq += acc[i] * acc[i]; }
#pragma unroll
    for (int off = 16; off >= 1; off >>= 1) {
        sum += __shfl_xor_sync(0xFFFFFFFFu, sum, off);
        sq  += __shfl_xor_sync(0xFFFFFFFFu, sq, off);
    }
    float mean = sum * (1.f / NH);
    float var = sq * (1.f / NH) - mean * mean;
    float inv = rsqrtf(var + LN_EPS);

    const float4* g4 = (const float4*)gamma;
    const float4* b4 = (const float4*)beta;
    float4 ga = __ldg(g4 + lane * 2), gb = __ldg(g4 + lane * 2 + 1);
    float4 ba = __ldg(b4 + lane * 2), bb = __ldg(b4 + lane * 2 + 1);
    float gs[8] = {ga.x, ga.y, ga.z, ga.w, gb.x, gb.y, gb.z, gb.w};
    float bs[8] = {ba.x, ba.y, ba.z, ba.w, bb.x, bb.y, bb.z, bb.w};
    float r[8];
#pragma unroll
    for (int i = 0; i < 8; i++) {
        float y = (acc[i] - mean) * inv * gs[i] + bs[i];
        r[i] = 0.5f * y * (1.f + erff(y * 0.70710678118654752f));
    }
    float4* o4 = (float4*)(out + (size_t)w * NH);
    o4[lane * 2] = make_float4(r[0], r[1], r[2], r[3]);
    o4[lane * 2 + 1] = make_float4(r[4], r[5], r[6], r[7]);
}

// ---------------- launch ---------------------------------------------
extern "C" void kernel_launch(void* const* d_in, const int* in_sizes, int n_in,
                              void* d_out, int out_size) {
    const float* x    = (const float*)d_in[0];
    const int* rows   = (const int*)d_in[1];
    const int* cols   = (const int*)d_in[2];
    const float* vals = (const float*)d_in[3];
    const int* seqr   = (const int*)d_in[4];
    const int* resr   = (const int*)d_in[5];
    const float* W    = (const float*)d_in[6];
    const float* b    = (const float*)d_in[7];
    const float* gamma = (const float*)d_in[8];
    const float* beta  = (const float*)d_in[9];
    float* out = (float*)d_out;

    static __half *s0p = nullptr, *s1p, *s2p, *t2a, *t3a, *t3b;
    static cudaStream_t st2, st3;
    static cudaEvent_t evFork, evGemm, evCSR, evS1, evT2a, evT3a, evT3b;
    if (!s0p) {
        cudaGetSymbolAddress((void**)&s0p, g_state0);
        cudaGetSymbolAddress((void**)&s1p, g_state1);
        cudaGetSymbolAddress((void**)&s2p, g_state2);
        cudaGetSymbolAddress((void**)&t2a, g_t2a);
        cudaGetSymbolAddress((void**)&t3a, g_t3a);
        cudaGetSymbolAddress((void**)&t3b, g_t3b);
        cudaStreamCreateWithFlags(&st2, cudaStreamNonBlocking);
        cudaStreamCreateWithFlags(&st3, cudaStreamNonBlocking);
        cudaEventCreateWithFlags(&evFork, cudaEventDisableTiming);
        cudaEventCreateWithFlags(&evGemm, cudaEventDisableTiming);
        cudaEventCreateWithFlags(&evCSR, cudaEventDisableTiming);
        cudaEventCreateWithFlags(&evS1, cudaEventDisableTiming);
        cudaEventCreateWithFlags(&evT2a, cudaEventDisableTiming);
        cudaEventCreateWithFlags(&evT3a, cudaEventDisableTiming);
        cudaEventCreateWithFlags(&evT3b, cudaEventDisableTiming);
    }

    const int spmm_blocks = (NNODES + 7) / 8;  // warp per row, 8 warps/block
    const int e4_blocks = (NADJ * NEDGE / 4 + 255) / 256;

    // fork: GEMM on st2 runs concurrently with the CSR build chain
    cudaEventRecord(evFork, 0);
    cudaStreamWaitEvent(st2, evFork, 0);
    gemm_tf32_kernel<<<dim3((NNODES + GBM - 1) / GBM, NH / GBN), 256, 0, st2>>>(x, W, b, s0p);
    cudaEventRecord(evGemm, st2);

    // CSR build on the main (captured) stream
    decode_idx_kernel<<<1, 1>>>(seqr, resr);
    zero_cnt_kernel<<<(NADJ * NNODES + 255) / 256, 256>>>();
    hist_kernel<<<e4_blocks, 256>>>((const int4*)rows);
    scanA_kernel<<<NADJ * BLK_PER_ADJ, SCAN_B>>>();
    scanB_kernel<<<1, 512>>>();
    scanC_kernel<<<NADJ * BLK_PER_ADJ, SCAN_B>>>();
    scatter_kernel<<<e4_blocks, 256>>>((const int4*)rows, (const int4*)cols,
                                       (const float4*)vals);
    cudaEventRecord(evCSR, 0);

    // st2 (has s0 after gemm): independent residual terms off s0
    cudaStreamWaitEvent(st2, evCSR, 0);
    spmm_kernel<0><<<spmm_blocks, 256, 0, st2>>>(s0p, 3, nullptr, t2a);  // t2a = res0@s0
    cudaEventRecord(evT2a, st2);
    spmm_kernel<0><<<spmm_blocks, 256, 0, st2>>>(s0p, 4, nullptr, t3a);  // t3a = res1@s0
    cudaEventRecord(evT3a, st2);

    // main: sequential chain
    cudaStreamWaitEvent(0, evGemm, 0);
    spmm_kernel<0><<<spmm_blocks, 256>>>(s0p, 0, nullptr, s1p);          // s1 = seq0@s0
    cudaEventRecord(evS1, 0);

    // st3: t3b = res2@s1 (needs s1; CSR done before evS1 by main-stream order)
    cudaStreamWaitEvent(st3, evS1, 0);
    spmm_kernel<0><<<spmm_blocks, 256, 0, st3>>>(s1p, 5, nullptr, t3b);
    cudaEventRecord(evT3b, st3);

    // main: s2 = seq1@s1 + t2a
    cudaStreamWaitEvent(0, evT2a, 0);
    spmm_kernel<1><<<spmm_blocks, 256>>>(s1p, 1, t2a, s2p);

    // main: out = LN_GELU(seq2@s2 + t3a + t3b)
    cudaStreamWaitEvent(0, evT3a, 0);
    cudaStreamWaitEvent(0, evT3b, 0);
    spmm_ln_gelu_kernel<<<spmm_blocks, 256>>>(s2p, 2, t3a, t3b, gamma, beta, out);
}